// round 15
// baseline (speedup 1.0000x reference)
#include <cuda_runtime.h>
#include <cuda_fp16.h>
#include <cuda_pipeline.h>
#include <stdint.h>

// ---------------- problem constants ----------------
#define BSZ   8
#define CIN   256
#define NYv   80
#define NXv   80
#define CC    256
#define HW    (NYv * NXv)        // 6400
#define NPIX  (BSZ * HW)         // 51200
#define NPTS  16384
#define KD    (CC * 9)           // 2304
#define NOUT  85

// ---------------- device scratch ----------------
__device__ __align__(16) __half g_x[(size_t)NPIX * CIN];       // x transposed fp16
__device__ __align__(16) __half g_s[(size_t)NPIX * CC];        // stem out fp16 channel-last
__device__ __align__(16) __half g_sw[(size_t)CC * CIN];        // stem W fp16 [o][c]
__device__ __align__(16) __half g_cw[(size_t)512 * KD];        // conv W fp16 [o512][q*256+c]
__device__ __align__(16) __half g_featH[(size_t)NPTS * 512];   // [n][cls256|reg256] fp16
__device__ __align__(16) __half g_predw2[128 * 512];           // padded pred W fp16
__device__ float g_predb[128];
__device__ int   g_sb[NPTS], g_sy[NPTS], g_sx[NPTS];

__device__ __forceinline__ float silu(float v) {
    return v * (1.0f / (1.0f + __expf(-v)));
}

// ================= warp MMA primitives =================
__device__ __forceinline__ void mma16816(float* d, const uint32_t* a, uint32_t b0, uint32_t b1) {
    asm volatile(
        "mma.sync.aligned.m16n8k16.row.col.f32.f16.f16.f32 "
        "{%0,%1,%2,%3}, {%4,%5,%6,%7}, {%8,%9}, {%0,%1,%2,%3};"
        : "+f"(d[0]), "+f"(d[1]), "+f"(d[2]), "+f"(d[3])
        : "r"(a[0]), "r"(a[1]), "r"(a[2]), "r"(a[3]), "r"(b0), "r"(b1));
}
__device__ __forceinline__ void ldsm4(uint32_t* r, uint32_t addr) {
    asm volatile("ldmatrix.sync.aligned.m8n8.x4.shared.b16 {%0,%1,%2,%3}, [%4];"
        : "=r"(r[0]), "=r"(r[1]), "=r"(r[2]), "=r"(r[3]) : "r"(addr));
}
__device__ __forceinline__ uint32_t smem_u32(const void* p) {
    uint32_t a;
    asm("{ .reg .u64 t; cvta.to.shared.u64 t, %1; cvt.u32.u64 %0, t; }" : "=r"(a) : "l"(p));
    return a;
}

// ---- smem rows: 64 halves = 128B, xor swizzle on 16B chunks ----
#define A_TILE 16384             // 128 rows x 128B
#define B_TILE 32768             // 256 rows x 128B
// conv: 2 stages x 2 chunks x (A 16K + B 32K) = 192KB, occ-1, 512 thr
#define CV_SMEM (4 * A_TILE + 4 * B_TILE)
#define ST_SMEM (2 * A_TILE + 2 * B_TILE)        // stem: 2-stage, 96KB (512 thr)
#define PR_SMEM (4 * A_TILE)                     // pred: 2-stage, 64KB

// ---- fragment load / mma helpers (64x32 warp tile) ----
__device__ __forceinline__ void ld_a(uint32_t abase, int wm, int lane, int ks, uint32_t a[4][4]) {
    const int ar = lane & 15, ac = lane >> 4;
    #pragma unroll
    for (int i = 0; i < 4; i++) {
        int row = wm * 64 + i * 16 + ar;
        int ch  = (ks * 2 + ac) ^ (row & 7);
        ldsm4(a[i], abase + row * 128 + ch * 16);
    }
}
__device__ __forceinline__ void ld_b(uint32_t bbase, int wn, int lane, int ks, uint32_t b[2][4]) {
    const int bn = (lane & 7) + ((lane >> 4) << 3);
    const int bk = (lane >> 3) & 1;
    #pragma unroll
    for (int j = 0; j < 2; j++) {
        int n  = wn * 32 + j * 16 + bn;
        int ch = (ks * 2 + bk) ^ (n & 7);
        ldsm4(b[j], bbase + n * 128 + ch * 16);
    }
}
__device__ __forceinline__ void do_mma(float acc[4][4][4], uint32_t a[4][4], uint32_t b[2][4]) {
    #pragma unroll
    for (int i = 0; i < 4; i++)
        #pragma unroll
        for (int jj = 0; jj < 4; jj++)
            mma16816(acc[i][jj], a[i], b[jj >> 1][(jj & 1) * 2], b[jj >> 1][(jj & 1) * 2 + 1]);
}

// 64x32 warp-tile, one 64-K chunk (plain; used by stem/pred)
__device__ __forceinline__ void compute_stage(uint32_t abase, uint32_t bbase,
                                              int wm, int wn, int lane,
                                              float acc[4][4][4]) {
    #pragma unroll
    for (int ks = 0; ks < 4; ks++) {
        uint32_t a[4][4], b[2][4];
        ld_a(abase, wm, lane, ks, a);
        ld_b(bbase, wn, lane, ks, b);
        do_mma(acc, a, b);
    }
}

// 128-K stage over two chunk buffers with frag double-buffering (conv).
__device__ __forceinline__ void compute_stage128(uint32_t a0base, uint32_t b0base,
                                                 uint32_t a1base, uint32_t b1base,
                                                 int wm, int wn, int lane,
                                                 float acc[4][4][4]) {
    uint32_t A0[4][4], B0[2][4], A1[4][4], B1[2][4];
    ld_a(a0base, wm, lane, 0, A0);
    ld_b(b0base, wn, lane, 0, B0);
    #pragma unroll
    for (int p = 0; p < 4; p++) {
        int s1 = 2 * p + 1;
        uint32_t ab = (s1 >= 4) ? a1base : a0base;
        uint32_t bb = (s1 >= 4) ? b1base : b0base;
        ld_a(ab, wm, lane, s1 & 3, A1);
        ld_b(bb, wn, lane, s1 & 3, B1);
        do_mma(acc, A0, B0);
        if (p < 3) {
            int s2 = 2 * p + 2;
            uint32_t ab2 = (s2 >= 4) ? a1base : a0base;
            uint32_t bb2 = (s2 >= 4) ? b1base : b0base;
            ld_a(ab2, wm, lane, s2 & 3, A0);
            ld_b(bb2, wn, lane, s2 & 3, B0);
        }
        do_mma(acc, A1, B1);
    }
}

// ================= prep_x: x [b][c][p] -> g_x [b*HW+p][c] fp16 ========
__global__ void prep_x(const float* __restrict__ x) {
    __shared__ float t[32][33];
    int p0 = blockIdx.x * 32, c0 = blockIdx.y * 32, b = blockIdx.z;
    int tx = threadIdx.x, ty = threadIdx.y;
    #pragma unroll
    for (int j = 0; j < 4; j++) {
        int c = c0 + ty + j * 8;
        t[ty + j * 8][tx] = x[((size_t)b * CIN + c) * HW + p0 + tx];
    }
    __syncthreads();
    #pragma unroll
    for (int j = 0; j < 4; j++) {
        int p = p0 + ty + j * 8;
        g_x[((size_t)b * HW + p) * CIN + c0 + tx] = __float2half_rn(t[tx][ty + j * 8]);
    }
}

// ============ fused prep: conv W, stem W, pred W2+biases, index decode ======
#define CW_N (512 * KD)          // 1179648
#define SW_N (CC * CIN)          // 65536
#define PW_N (128 * 512)         // 65536
#define PREP_TOTAL (CW_N + SW_N + PW_N + NPTS)
__global__ void prep_weights(const float* __restrict__ wc, const float* __restrict__ wr,
                             const float* __restrict__ sw,
                             const float* __restrict__ cpw, const float* __restrict__ cpb,
                             const float* __restrict__ rpw, const float* __restrict__ rpb,
                             const float* __restrict__ opw, const float* __restrict__ opb,
                             const int* __restrict__ idx32) {
    int idx = blockIdx.x * blockDim.x + threadIdx.x;
    if (idx < CW_N) {
        int o = idx / KD, r = idx % KD;
        int q = r >> 8, c = r & 255;
        int korig = c * 9 + q;
        float v = (o < 256) ? wc[(size_t)o * KD + korig] : wr[(size_t)(o - 256) * KD + korig];
        g_cw[idx] = __float2half_rn(v);
        return;
    }
    int j = idx - CW_N;
    if (j < SW_N) { g_sw[j] = __float2half_rn(sw[j]); return; }
    j -= SW_N;
    if (j < PW_N) {
        int o = j >> 9, k = j & 511;
        float v = 0.f;
        if (o < 4)       { if (k >= 256) v = rpw[o * 256 + (k - 256)]; }
        else if (o == 4) { if (k >= 256) v = opw[k - 256]; }
        else if (o < 85) { if (k < 256)  v = cpw[(o - 5) * 256 + k]; }
        g_predw2[j] = __float2half_rn(v);
        if (k == 0) {
            float bv = 0.f;
            if (o < 4) bv = rpb[o]; else if (o == 4) bv = opb[0]; else if (o < 85) bv = cpb[o - 5];
            g_predb[o] = bv;
        }
        return;
    }
    j -= PW_N;
    if (j < NPTS) {
        bool is64 = true;
        #pragma unroll
        for (int k = 1; k < 24; k += 2) is64 = is64 && (idx32[k] == 0);
        int bi, yi, xi;
        if (is64) { bi = idx32[6 * j]; yi = idx32[6 * j + 2]; xi = idx32[6 * j + 4]; }
        else      { bi = idx32[3 * j]; yi = idx32[3 * j + 1]; xi = idx32[3 * j + 2]; }
        g_sb[j] = bi; g_sy[j] = yi; g_sx[j] = xi;
    }
}

// ================= stem GEMM (fp16, 2-stage, 512 thr, N=256) ===============
__global__ __launch_bounds__(512) void stem_gemm(const float* __restrict__ bias) {
    extern __shared__ char sm[];
    uint32_t smb = smem_u32(sm);
    int tid = threadIdx.x, lane = tid & 31, wid = tid >> 5;
    int wm = wid & 1, wn = wid >> 1;    // wn 0..7
    int m0 = blockIdx.x * 128;

    float acc[4][4][4] = {};
    const int NCH = CIN / 64;   // 4

    auto load_stage = [&](int buf, int i) {
        int kc = i * 64;
        char* A = sm + buf * A_TILE;
        char* B = sm + 2 * A_TILE + buf * B_TILE;
        #pragma unroll
        for (int j2 = 0; j2 < 2; j2++) {
            int l = tid + 512 * j2;
            int row = l >> 3, ch = l & 7;
            int sw = (ch ^ (row & 7)) * 16 + row * 128;
            __pipeline_memcpy_async(A + sw, g_x + ((size_t)(m0 + row) * CIN + kc + ch * 8), 16);
        }
        #pragma unroll
        for (int j2 = 0; j2 < 4; j2++) {
            int l = tid + 512 * j2;
            int row = l >> 3, ch = l & 7;
            int sw = (ch ^ (row & 7)) * 16 + row * 128;
            __pipeline_memcpy_async(B + sw, g_sw + ((size_t)row * CIN + kc + ch * 8), 16);
        }
    };

    load_stage(0, 0); __pipeline_commit();
    for (int i = 0; i < NCH; i++) {
        __pipeline_wait_prior(0);
        __syncthreads();
        if (i + 1 < NCH) { load_stage((i + 1) & 1, i + 1); __pipeline_commit(); }
        compute_stage(smb + (i & 1) * A_TILE, smb + 2 * A_TILE + (i & 1) * B_TILE,
                      wm, wn, lane, acc);
    }

    int g = lane >> 2, tg = lane & 3;
    #pragma unroll
    for (int i = 0; i < 4; i++) {
        #pragma unroll
        for (int jj = 0; jj < 4; jj++) {
            int col = wn * 32 + jj * 8 + tg * 2;
            float b0 = bias[col], b1 = bias[col + 1];
            int r0 = m0 + wm * 64 + i * 16 + g;
            #pragma unroll
            for (int h = 0; h < 2; h++) {
                int pix = r0 + h * 8;
                __half2 hp;
                hp.x = __float2half_rn(silu(acc[i][jj][h * 2 + 0] + b0));
                hp.y = __float2half_rn(silu(acc[i][jj][h * 2 + 1] + b1));
                *(__half2*)&g_s[(size_t)pix * CC + col] = hp;
            }
        }
    }
}

// ====== conv GEMM: 512 thr, 16 warps (2x8), K-stage 128, frag ping-pong =====
// grid (128, 2). M=128 pts, N=256 outs, K=2304 -> 18 stages of 128.
__global__ __launch_bounds__(512) void conv_gemm(const float* __restrict__ bc,
                                                 const float* __restrict__ br) {
    extern __shared__ char sm[];
    __shared__ int ssb[128], ssy[128], ssx[128];
    uint32_t smb = smem_u32(sm);
    int tid = threadIdx.x, lane = tid & 31, wid = tid >> 5;
    int wm = wid & 1, wn = wid >> 1;       // wn 0..7
    int n0 = blockIdx.x * 128;
    int set = blockIdx.y;                  // 0=cls, 1=reg
    int oB = set * 256;

    if (tid < 128) { ssb[tid] = g_sb[n0 + tid]; ssy[tid] = g_sy[n0 + tid]; ssx[tid] = g_sx[n0 + tid]; }
    __syncthreads();

    float acc[4][4][4] = {};
    const int NST = KD / 128;   // 18 stages, 2 chunks each

    auto load_chunk = [&](int sub, int c) {
        int kc = c * 64;
        int q = kc >> 8, c0 = kc & 255;
        int kh = q / 3, kw = q - kh * 3;
        char* A = sm + sub * A_TILE;
        char* B = sm + 4 * A_TILE + sub * B_TILE;
        #pragma unroll
        for (int j2 = 0; j2 < 2; j2++) {
            int l = tid + 512 * j2;
            int row = l >> 3, ch = l & 7;
            int sw = (ch ^ (row & 7)) * 16 + row * 128;
            int y = ssy[row] + kh - 1, xx = ssx[row] + kw - 1;
            bool ok = ((unsigned)y < (unsigned)NYv) && ((unsigned)xx < (unsigned)NXv);
            const __half* gp = g_s +
                ((((size_t)ssb[row] * NYv + (ok ? y : 0)) * NXv + (ok ? xx : 0)) * CC + c0 + ch * 8);
            __pipeline_memcpy_async(A + sw, gp, 16, ok ? 0 : 16);   // zfill when OOB
        }
        #pragma unroll
        for (int j2 = 0; j2 < 4; j2++) {
            int l = tid + 512 * j2;
            int row = l >> 3, ch = l & 7;
            int sw = (ch ^ (row & 7)) * 16 + row * 128;
            __pipeline_memcpy_async(B + sw, g_cw + ((size_t)(oB + row) * KD + kc + ch * 8), 16);
        }
    };

    load_chunk(0, 0); load_chunk(1, 1); __pipeline_commit();    // stage 0
    for (int s = 0; s < NST; s++) {
        __pipeline_wait_prior(0);
        __syncthreads();
        int sb = (s & 1) * 2;
        if (s + 1 < NST) {
            int nb = ((s + 1) & 1) * 2;
            load_chunk(nb, 2 * s + 2); load_chunk(nb + 1, 2 * s + 3);
            __pipeline_commit();
        }
        compute_stage128(smb + sb * A_TILE,       smb + 4 * A_TILE + sb * B_TILE,
                         smb + (sb + 1) * A_TILE, smb + 4 * A_TILE + (sb + 1) * B_TILE,
                         wm, wn, lane, acc);
    }

    const float* bp = set ? br : bc;
    int g = lane >> 2, tg = lane & 3;
    #pragma unroll
    for (int i = 0; i < 4; i++) {
        #pragma unroll
        for (int jj = 0; jj < 4; jj++) {
            int col = wn * 32 + jj * 8 + tg * 2;      // 0..255 within set
            float b0 = bp[col], b1 = bp[col + 1];
            int r0 = n0 + wm * 64 + i * 16 + g;
            #pragma unroll
            for (int h = 0; h < 2; h++) {
                int n = r0 + h * 8;
                __half2 hp;
                hp.x = __float2half_rn(silu(acc[i][jj][h * 2 + 0] + b0));
                hp.y = __float2half_rn(silu(acc[i][jj][h * 2 + 1] + b1));
                *(__half2*)&g_featH[(size_t)n * 512 + set * 256 + col] = hp;
            }
        }
    }
}

// ================= pred GEMM (fp16 mma, 2-stage) =================
__global__ __launch_bounds__(256, 2) void pred_gemm(float* __restrict__ out) {
    extern __shared__ char sm[];
    uint32_t smb = smem_u32(sm);
    int tid = threadIdx.x, lane = tid & 31, wid = tid >> 5;
    int wm = wid & 1, wn = wid >> 1;
    int n0 = blockIdx.x * 128;

    float acc[4][4][4] = {};
    const int NCH = 512 / 64;   // 8

    auto load_stage = [&](int buf, int i) {
        int kc = i * 64;
        char* A = sm + buf * A_TILE;
        char* B = sm + 2 * A_TILE + buf * A_TILE;
        #pragma unroll
        for (int j2 = 0; j2 < 4; j2++) {
            int l = tid + 256 * j2;
            int row = l >> 3, ch = l & 7;
            int sw = (ch ^ (row & 7)) * 16 + row * 128;
            __pipeline_memcpy_async(A + sw, g_featH + ((size_t)(n0 + row) * 512 + kc + ch * 8), 16);
            __pipeline_memcpy_async(B + sw, g_predw2 + ((size_t)row * 512 + kc + ch * 8), 16);
        }
    };

    load_stage(0, 0); __pipeline_commit();
    for (int i = 0; i < NCH; i++) {
        __pipeline_wait_prior(0);
        __syncthreads();
        if (i + 1 < NCH) { load_stage((i + 1) & 1, i + 1); __pipeline_commit(); }
        compute_stage(smb + (i & 1) * A_TILE, smb + 2 * A_TILE + (i & 1) * A_TILE,
                      wm, wn, lane, acc);
    }

    int g = lane >> 2, tg = lane & 3;
    #pragma unroll
    for (int i = 0; i < 4; i++) {
        #pragma unroll
        for (int jj = 0; jj < 4; jj++) {
            int col = wn * 32 + jj * 8 + tg * 2;     // 0..127
            int r0 = n0 + wm * 64 + i * 16 + g;
            if (col < NOUT) {
                float bv = g_predb[col];
                out[(size_t)r0 * NOUT + col]       = acc[i][jj][0] + bv;
                out[(size_t)(r0 + 8) * NOUT + col] = acc[i][jj][2] + bv;
            }
            if (col + 1 < NOUT) {
                float bv = g_predb[col + 1];
                out[(size_t)r0 * NOUT + col + 1]       = acc[i][jj][1] + bv;
                out[(size_t)(r0 + 8) * NOUT + col + 1] = acc[i][jj][3] + bv;
            }
        }
    }
}

// ================= launch =================
extern "C" void kernel_launch(void* const* d_in, const int* in_sizes, int n_in,
                              void* d_out, int out_size) {
    const float* x          = (const float*)d_in[0];
    const int*   indices32  = (const int*)d_in[1];
    const float* stem_w     = (const float*)d_in[2];
    const float* stem_b     = (const float*)d_in[3];
    const float* cls_conv_w = (const float*)d_in[4];
    const float* cls_conv_b = (const float*)d_in[5];
    const float* reg_conv_w = (const float*)d_in[6];
    const float* reg_conv_b = (const float*)d_in[7];
    const float* cls_pred_w = (const float*)d_in[8];
    const float* cls_pred_b = (const float*)d_in[9];
    const float* reg_pred_w = (const float*)d_in[10];
    const float* reg_pred_b = (const float*)d_in[11];
    const float* obj_pred_w = (const float*)d_in[12];
    const float* obj_pred_b = (const float*)d_in[13];
    float* out = (float*)d_out;

    cudaFuncSetAttribute(stem_gemm, cudaFuncAttributeMaxDynamicSharedMemorySize, ST_SMEM);
    cudaFuncSetAttribute(conv_gemm, cudaFuncAttributeMaxDynamicSharedMemorySize, CV_SMEM);
    cudaFuncSetAttribute(pred_gemm, cudaFuncAttributeMaxDynamicSharedMemorySize, PR_SMEM);

    dim3 gx(HW / 32, CIN / 32, BSZ);
    prep_x<<<gx, dim3(32, 8)>>>(x);
    prep_weights<<<(PREP_TOTAL + 255) / 256, 256>>>(
        cls_conv_w, reg_conv_w, stem_w,
        cls_pred_w, cls_pred_b, reg_pred_w, reg_pred_b, obj_pred_w, obj_pred_b,
        indices32);

    stem_gemm<<<NPIX / 128, 512, ST_SMEM>>>(stem_b);
    conv_gemm<<<dim3(NPTS / 128, 2), 512, CV_SMEM>>>(cls_conv_b, reg_conv_b);
    pred_gemm<<<NPTS / 128, 256, PR_SMEM>>>(out);
}

// round 17
// speedup vs baseline: 1.0406x; 1.0406x over previous
#include <cuda_runtime.h>
#include <cuda_fp16.h>
#include <cuda_pipeline.h>
#include <stdint.h>

// ---------------- problem constants ----------------
#define BSZ   8
#define CIN   256
#define NYv   80
#define NXv   80
#define CC    256
#define HW    (NYv * NXv)        // 6400
#define NPIX  (BSZ * HW)         // 51200
#define NPTS  16384
#define KD    (CC * 9)           // 2304
#define NOUT  85

// ---------------- device scratch ----------------
__device__ __align__(16) __half g_x[(size_t)NPIX * CIN];       // x transposed fp16
__device__ __align__(16) __half g_s[(size_t)NPIX * CC];        // stem out fp16 channel-last
__device__ __align__(16) __half g_sw[(size_t)CC * CIN];        // stem W fp16 [o][c]
__device__ __align__(16) __half g_cw[(size_t)512 * KD];        // conv W fp16 [o512][q*256+c]
__device__ __align__(16) __half g_featH[(size_t)NPTS * 512];   // [n][cls256|reg256] fp16
__device__ __align__(16) __half g_predw2[128 * 512];           // padded pred W fp16
__device__ float g_predb[128];
__device__ int   g_sb[NPTS], g_sy[NPTS], g_sx[NPTS];

__device__ __forceinline__ float silu(float v) {
    return v * (1.0f / (1.0f + __expf(-v)));
}

// ================= warp MMA primitives =================
__device__ __forceinline__ void mma16816(float* d, const uint32_t* a, uint32_t b0, uint32_t b1) {
    asm volatile(
        "mma.sync.aligned.m16n8k16.row.col.f32.f16.f16.f32 "
        "{%0,%1,%2,%3}, {%4,%5,%6,%7}, {%8,%9}, {%0,%1,%2,%3};"
        : "+f"(d[0]), "+f"(d[1]), "+f"(d[2]), "+f"(d[3])
        : "r"(a[0]), "r"(a[1]), "r"(a[2]), "r"(a[3]), "r"(b0), "r"(b1));
}
__device__ __forceinline__ void ldsm4(uint32_t* r, uint32_t addr) {
    asm volatile("ldmatrix.sync.aligned.m8n8.x4.shared.b16 {%0,%1,%2,%3}, [%4];"
        : "=r"(r[0]), "=r"(r[1]), "=r"(r[2]), "=r"(r[3]) : "r"(addr));
}
__device__ __forceinline__ uint32_t smem_u32(const void* p) {
    uint32_t a;
    asm("{ .reg .u64 t; cvta.to.shared.u64 t, %1; cvt.u32.u64 %0, t; }" : "=r"(a) : "l"(p));
    return a;
}

// ---- smem rows: 64 halves = 128B, xor swizzle on 16B chunks ----
#define A_TILE 16384             // 128 rows x 128B
#define B_TILE 32768             // 256 rows x 128B
// conv: 2 stages x 2 chunks x (A 16K + B 32K) = 192KB, occ-1, 512 thr
#define CV_SMEM (4 * A_TILE + 4 * B_TILE)
#define ST_SMEM (2 * A_TILE + 2 * B_TILE)        // stem: 2-stage, 96KB (512 thr)
#define PR_SMEM (4 * A_TILE)                     // pred: 2-stage, 64KB

// 64x32 warp-tile stage
__device__ __forceinline__ void compute_stage(uint32_t abase, uint32_t bbase,
                                              int wm, int wn, int lane,
                                              float acc[4][4][4]) {
    const int ar = lane & 15, ac = lane >> 4;
    const int bn = (lane & 7) + ((lane >> 4) << 3);
    const int bk = (lane >> 3) & 1;
    #pragma unroll
    for (int ks = 0; ks < 4; ks++) {
        uint32_t a[4][4], b[2][4];
        #pragma unroll
        for (int i = 0; i < 4; i++) {
            int row = wm * 64 + i * 16 + ar;
            int ch  = (ks * 2 + ac) ^ (row & 7);
            ldsm4(a[i], abase + row * 128 + ch * 16);
        }
        #pragma unroll
        for (int j = 0; j < 2; j++) {
            int n  = wn * 32 + j * 16 + bn;
            int ch = (ks * 2 + bk) ^ (n & 7);
            ldsm4(b[j], bbase + n * 128 + ch * 16);
        }
        #pragma unroll
        for (int i = 0; i < 4; i++)
            #pragma unroll
            for (int jj = 0; jj < 4; jj++)
                mma16816(acc[i][jj], a[i], b[jj >> 1][(jj & 1) * 2], b[jj >> 1][(jj & 1) * 2 + 1]);
    }
}

// ================= prep_x: x [b][c][p] -> g_x [b*HW+p][c] fp16 ========
__global__ void prep_x(const float* __restrict__ x) {
    __shared__ float t[32][33];
    int p0 = blockIdx.x * 32, c0 = blockIdx.y * 32, b = blockIdx.z;
    int tx = threadIdx.x, ty = threadIdx.y;
    #pragma unroll
    for (int j = 0; j < 4; j++) {
        int c = c0 + ty + j * 8;
        t[ty + j * 8][tx] = x[((size_t)b * CIN + c) * HW + p0 + tx];
    }
    __syncthreads();
    #pragma unroll
    for (int j = 0; j < 4; j++) {
        int p = p0 + ty + j * 8;
        g_x[((size_t)b * HW + p) * CIN + c0 + tx] = __float2half_rn(t[tx][ty + j * 8]);
    }
}

// ============ fused prep: conv W, stem W, pred W2+biases, index decode ======
#define CW_N (512 * KD)          // 1179648
#define SW_N (CC * CIN)          // 65536
#define PW_N (128 * 512)         // 65536
#define PREP_TOTAL (CW_N + SW_N + PW_N + NPTS)
__global__ void prep_weights(const float* __restrict__ wc, const float* __restrict__ wr,
                             const float* __restrict__ sw,
                             const float* __restrict__ cpw, const float* __restrict__ cpb,
                             const float* __restrict__ rpw, const float* __restrict__ rpb,
                             const float* __restrict__ opw, const float* __restrict__ opb,
                             const int* __restrict__ idx32) {
    int idx = blockIdx.x * blockDim.x + threadIdx.x;
    if (idx < CW_N) {
        int o = idx / KD, r = idx % KD;
        int q = r >> 8, c = r & 255;
        int korig = c * 9 + q;
        float v = (o < 256) ? wc[(size_t)o * KD + korig] : wr[(size_t)(o - 256) * KD + korig];
        g_cw[idx] = __float2half_rn(v);
        return;
    }
    int j = idx - CW_N;
    if (j < SW_N) { g_sw[j] = __float2half_rn(sw[j]); return; }
    j -= SW_N;
    if (j < PW_N) {
        int o = j >> 9, k = j & 511;
        float v = 0.f;
        if (o < 4)       { if (k >= 256) v = rpw[o * 256 + (k - 256)]; }
        else if (o == 4) { if (k >= 256) v = opw[k - 256]; }
        else if (o < 85) { if (k < 256)  v = cpw[(o - 5) * 256 + k]; }
        g_predw2[j] = __float2half_rn(v);
        if (k == 0) {
            float bv = 0.f;
            if (o < 4) bv = rpb[o]; else if (o == 4) bv = opb[0]; else if (o < 85) bv = cpb[o - 5];
            g_predb[o] = bv;
        }
        return;
    }
    j -= PW_N;
    if (j < NPTS) {
        bool is64 = true;
        #pragma unroll
        for (int k = 1; k < 24; k += 2) is64 = is64 && (idx32[k] == 0);
        int bi, yi, xi;
        if (is64) { bi = idx32[6 * j]; yi = idx32[6 * j + 2]; xi = idx32[6 * j + 4]; }
        else      { bi = idx32[3 * j]; yi = idx32[3 * j + 1]; xi = idx32[3 * j + 2]; }
        g_sb[j] = bi; g_sy[j] = yi; g_sx[j] = xi;
    }
}

// ================= stem GEMM (fp16, 2-stage, 512 thr, N=256) ===============
__global__ __launch_bounds__(512) void stem_gemm(const float* __restrict__ bias) {
    extern __shared__ char sm[];
    uint32_t smb = smem_u32(sm);
    int tid = threadIdx.x, lane = tid & 31, wid = tid >> 5;
    int wm = wid & 1, wn = wid >> 1;    // wn 0..7
    int m0 = blockIdx.x * 128;

    float acc[4][4][4] = {};
    const int NCH = CIN / 64;   // 4

    auto load_stage = [&](int buf, int i) {
        int kc = i * 64;
        char* A = sm + buf * A_TILE;
        char* B = sm + 2 * A_TILE + buf * B_TILE;
        #pragma unroll
        for (int j2 = 0; j2 < 2; j2++) {
            int l = tid + 512 * j2;
            int row = l >> 3, ch = l & 7;
            int sw = (ch ^ (row & 7)) * 16 + row * 128;
            __pipeline_memcpy_async(A + sw, g_x + ((size_t)(m0 + row) * CIN + kc + ch * 8), 16);
        }
        #pragma unroll
        for (int j2 = 0; j2 < 4; j2++) {
            int l = tid + 512 * j2;
            int row = l >> 3, ch = l & 7;
            int sw = (ch ^ (row & 7)) * 16 + row * 128;
            __pipeline_memcpy_async(B + sw, g_sw + ((size_t)row * CIN + kc + ch * 8), 16);
        }
    };

    load_stage(0, 0); __pipeline_commit();
    for (int i = 0; i < NCH; i++) {
        __pipeline_wait_prior(0);
        __syncthreads();
        if (i + 1 < NCH) { load_stage((i + 1) & 1, i + 1); __pipeline_commit(); }
        compute_stage(smb + (i & 1) * A_TILE, smb + 2 * A_TILE + (i & 1) * B_TILE,
                      wm, wn, lane, acc);
    }

    int g = lane >> 2, tg = lane & 3;
    #pragma unroll
    for (int i = 0; i < 4; i++) {
        #pragma unroll
        for (int jj = 0; jj < 4; jj++) {
            int col = wn * 32 + jj * 8 + tg * 2;
            float b0 = bias[col], b1 = bias[col + 1];
            int r0 = m0 + wm * 64 + i * 16 + g;
            #pragma unroll
            for (int h = 0; h < 2; h++) {
                int pix = r0 + h * 8;
                __half2 hp;
                hp.x = __float2half_rn(silu(acc[i][jj][h * 2 + 0] + b0));
                hp.y = __float2half_rn(silu(acc[i][jj][h * 2 + 1] + b1));
                *(__half2*)&g_s[(size_t)pix * CC + col] = hp;
            }
        }
    }
}

// ====== conv GEMM: 512 thr, 16 warps, K-stage 128, precomputed gather ======
// grid (128, 2). M=128 pts, N=256 outs, K=2304 -> 18 stages of 128.
__global__ __launch_bounds__(512) void conv_gemm(const float* __restrict__ bc,
                                                 const float* __restrict__ br) {
    extern __shared__ char sm[];
    __shared__ int ssoff[128];     // base element offset ((b*NY+y)*NX+x)*CC
    __shared__ int ssmask[128];    // bit q: tap q in-bounds
    uint32_t smb = smem_u32(sm);
    int tid = threadIdx.x, lane = tid & 31, wid = tid >> 5;
    int wm = wid & 1, wn = wid >> 1;       // wn 0..7
    int n0 = blockIdx.x * 128;
    int set = blockIdx.y;                  // 0=cls, 1=reg
    int oB = set * 256;

    if (tid < 128) {
        int b = g_sb[n0 + tid], y = g_sy[n0 + tid], x = g_sx[n0 + tid];
        ssoff[tid] = ((b * NYv + y) * NXv + x) * CC;
        int m = 0;
        #pragma unroll
        for (int q = 0; q < 9; q++) {
            int kh = q / 3, kw = q - kh * 3;
            int yy = y + kh - 1, xx = x + kw - 1;
            if ((unsigned)yy < (unsigned)NYv && (unsigned)xx < (unsigned)NXv) m |= (1 << q);
        }
        ssmask[tid] = m;
    }
    __syncthreads();

    float acc[4][4][4] = {};
    const int NST = KD / 128;   // 18 stages, 2 chunks each

    auto load_chunk = [&](int sub, int c) {
        int kc = c * 64;
        int q = kc >> 8, c0 = kc & 255;
        int kh = q / 3, kw = q - kh * 3;
        int tapoff = ((kh - 1) * NXv + (kw - 1)) * CC + c0;   // uniform per chunk
        char* A = sm + sub * A_TILE;
        char* B = sm + 4 * A_TILE + sub * B_TILE;
        #pragma unroll
        for (int j2 = 0; j2 < 2; j2++) {
            int l = tid + 512 * j2;
            int row = l >> 3, ch = l & 7;
            int sw = (ch ^ (row & 7)) * 16 + row * 128;
            bool ok = (ssmask[row] >> q) & 1;
            int off = ok ? (ssoff[row] + tapoff) : 0;
            __pipeline_memcpy_async(A + sw, g_s + off + ch * 8, 16, ok ? 0 : 16);
        }
        #pragma unroll
        for (int j2 = 0; j2 < 4; j2++) {
            int l = tid + 512 * j2;
            int row = l >> 3, ch = l & 7;
            int sw = (ch ^ (row & 7)) * 16 + row * 128;
            __pipeline_memcpy_async(B + sw, g_cw + ((size_t)(oB + row) * KD + kc + ch * 8), 16);
        }
    };

    load_chunk(0, 0); load_chunk(1, 1); __pipeline_commit();    // stage 0
    for (int s = 0; s < NST; s++) {
        __pipeline_wait_prior(0);
        __syncthreads();
        int sb = (s & 1) * 2;
        if (s + 1 < NST) {
            int nb = ((s + 1) & 1) * 2;
            load_chunk(nb, 2 * s + 2); load_chunk(nb + 1, 2 * s + 3);
            __pipeline_commit();
        }
        compute_stage(smb + sb * A_TILE, smb + 4 * A_TILE + sb * B_TILE,
                      wm, wn, lane, acc);
        compute_stage(smb + (sb + 1) * A_TILE, smb + 4 * A_TILE + (sb + 1) * B_TILE,
                      wm, wn, lane, acc);
    }

    const float* bp = set ? br : bc;
    int g = lane >> 2, tg = lane & 3;
    #pragma unroll
    for (int i = 0; i < 4; i++) {
        #pragma unroll
        for (int jj = 0; jj < 4; jj++) {
            int col = wn * 32 + jj * 8 + tg * 2;      // 0..255 within set
            float b0 = bp[col], b1 = bp[col + 1];
            int r0 = n0 + wm * 64 + i * 16 + g;
            #pragma unroll
            for (int h = 0; h < 2; h++) {
                int n = r0 + h * 8;
                __half2 hp;
                hp.x = __float2half_rn(silu(acc[i][jj][h * 2 + 0] + b0));
                hp.y = __float2half_rn(silu(acc[i][jj][h * 2 + 1] + b1));
                *(__half2*)&g_featH[(size_t)n * 512 + set * 256 + col] = hp;
            }
        }
    }
}

// ================= pred GEMM (fp16 mma, 2-stage) =================
__global__ __launch_bounds__(256, 2) void pred_gemm(float* __restrict__ out) {
    extern __shared__ char sm[];
    uint32_t smb = smem_u32(sm);
    int tid = threadIdx.x, lane = tid & 31, wid = tid >> 5;
    int wm = wid & 1, wn = wid >> 1;
    int n0 = blockIdx.x * 128;

    float acc[4][4][4] = {};
    const int NCH = 512 / 64;   // 8

    auto load_stage = [&](int buf, int i) {
        int kc = i * 64;
        char* A = sm + buf * A_TILE;
        char* B = sm + 2 * A_TILE + buf * A_TILE;
        #pragma unroll
        for (int j2 = 0; j2 < 4; j2++) {
            int l = tid + 256 * j2;
            int row = l >> 3, ch = l & 7;
            int sw = (ch ^ (row & 7)) * 16 + row * 128;
            __pipeline_memcpy_async(A + sw, g_featH + ((size_t)(n0 + row) * 512 + kc + ch * 8), 16);
            __pipeline_memcpy_async(B + sw, g_predw2 + ((size_t)row * 512 + kc + ch * 8), 16);
        }
    };

    load_stage(0, 0); __pipeline_commit();
    for (int i = 0; i < NCH; i++) {
        __pipeline_wait_prior(0);
        __syncthreads();
        if (i + 1 < NCH) { load_stage((i + 1) & 1, i + 1); __pipeline_commit(); }
        compute_stage(smb + (i & 1) * A_TILE, smb + 2 * A_TILE + (i & 1) * A_TILE,
                      wm, wn, lane, acc);
    }

    int g = lane >> 2, tg = lane & 3;
    #pragma unroll
    for (int i = 0; i < 4; i++) {
        #pragma unroll
        for (int jj = 0; jj < 4; jj++) {
            int col = wn * 32 + jj * 8 + tg * 2;     // 0..127
            int r0 = n0 + wm * 64 + i * 16 + g;
            if (col < NOUT) {
                float bv = g_predb[col];
                out[(size_t)r0 * NOUT + col]       = acc[i][jj][0] + bv;
                out[(size_t)(r0 + 8) * NOUT + col] = acc[i][jj][2] + bv;
            }
            if (col + 1 < NOUT) {
                float bv = g_predb[col + 1];
                out[(size_t)r0 * NOUT + col + 1]       = acc[i][jj][1] + bv;
                out[(size_t)(r0 + 8) * NOUT + col + 1] = acc[i][jj][3] + bv;
            }
        }
    }
}

// ================= launch =================
extern "C" void kernel_launch(void* const* d_in, const int* in_sizes, int n_in,
                              void* d_out, int out_size) {
    const float* x          = (const float*)d_in[0];
    const int*   indices32  = (const int*)d_in[1];
    const float* stem_w     = (const float*)d_in[2];
    const float* stem_b     = (const float*)d_in[3];
    const float* cls_conv_w = (const float*)d_in[4];
    const float* cls_conv_b = (const float*)d_in[5];
    const float* reg_conv_w = (const float*)d_in[6];
    const float* reg_conv_b = (const float*)d_in[7];
    const float* cls_pred_w = (const float*)d_in[8];
    const float* cls_pred_b = (const float*)d_in[9];
    const float* reg_pred_w = (const float*)d_in[10];
    const float* reg_pred_b = (const float*)d_in[11];
    const float* obj_pred_w = (const float*)d_in[12];
    const float* obj_pred_b = (const float*)d_in[13];
    float* out = (float*)d_out;

    cudaFuncSetAttribute(stem_gemm, cudaFuncAttributeMaxDynamicSharedMemorySize, ST_SMEM);
    cudaFuncSetAttribute(conv_gemm, cudaFuncAttributeMaxDynamicSharedMemorySize, CV_SMEM);
    cudaFuncSetAttribute(pred_gemm, cudaFuncAttributeMaxDynamicSharedMemorySize, PR_SMEM);

    dim3 gx(HW / 32, CIN / 32, BSZ);
    prep_x<<<gx, dim3(32, 8)>>>(x);
    prep_weights<<<(PREP_TOTAL + 255) / 256, 256>>>(
        cls_conv_w, reg_conv_w, stem_w,
        cls_pred_w, cls_pred_b, reg_pred_w, reg_pred_b, obj_pred_w, obj_pred_b,
        indices32);

    stem_gemm<<<NPIX / 128, 512, ST_SMEM>>>(stem_b);
    conv_gemm<<<dim3(NPTS / 128, 2), 512, CV_SMEM>>>(cls_conv_b, reg_conv_b);
    pred_gemm<<<NPTS / 128, 256, PR_SMEM>>>(out);
}